// round 7
// baseline (speedup 1.0000x reference)
#include <cuda_runtime.h>
#include <cstdint>

// Output: [B=16, T=50, H=100, W=100, P=25] fp32 = 200M elems = 800MB.
// Persistent single kernel: grid = 148 SMs x 8 CTAs = 1184 blocks, each
// grid-strides over contiguous 8192-float slices (~21 per block). Per slice:
// zero (8x STG.128 evict-first) -> __syncthreads (CTA-scope order) -> warps
// 0-1 recompute the <=50 candidate points of the <=2 bt-regions overlapping
// the slice and write 1.0f for those landing inside it. Exactly-once.

static constexpr int B = 16;
static constexpr int T = 50;
static constexpr int H = 100;
static constexpr int W = 100;
static constexpr int P = 25;
static constexpr unsigned BT_STRIDE = (unsigned)H * W * P;   // 250000

static constexpr int VPT = 8;                        // float4s per thread
static constexpr int ZTHREADS = 256;
static constexpr unsigned SLICE = ZTHREADS * VPT * 4;        // 8192 floats
static constexpr unsigned SLICE_V4 = ZTHREADS * VPT;         // 2048 float4s

static constexpr int PERSIST_BLOCKS = 148 * 8;       // 1184

__global__ void __launch_bounds__(ZTHREADS)
fused_raster_kernel(const float2* __restrict__ x,          // [B*T*P] (px,py)
                    const float2* __restrict__ resolution, // [B*T]
                    const float2* __restrict__ origin,     // [B*T]
                    float* __restrict__ out,
                    unsigned n_vec4, unsigned n_slices) {
    const unsigned w = threadIdx.x >> 5;
    const unsigned l = threadIdx.x & 31u;
    const unsigned n = n_vec4 * 4u;                  // 200,000,000 < 2^31

    for (unsigned slice = blockIdx.x; slice < n_slices; slice += gridDim.x) {
        // ---- Phase 1: zero this slice (8x STG.128, evict-first) ----
        const float4 z = make_float4(0.f, 0.f, 0.f, 0.f);
        const unsigned base = slice * SLICE_V4 + threadIdx.x;
#pragma unroll
        for (int k = 0; k < VPT; k++) {
            unsigned i = base + k * ZTHREADS;
            if (i < n_vec4) {
                __stcs(reinterpret_cast<float4*>(out) + i, z);
            }
        }

        // CTA-scope ordering: this slice's zeros precede its ones.
        __syncthreads();

        // ---- Phase 2: ones landing inside [s, e) ----
        const unsigned s = slice * SLICE;
        const unsigned e = (s + SLICE < n) ? (s + SLICE) : n;

        const unsigned bt0 = s / BT_STRIDE;          // const-div -> mul/shift
        const unsigned bt1 = (e - 1u) / BT_STRIDE;   // slice spans <=2 regions
        const unsigned nbt = bt1 - bt0 + 1u;         // 1 or 2

        if (w < nbt && l < (unsigned)P) {
            const unsigned bt = bt0 + w;
            const float2 pt = __ldg(&x[bt * P + l]);     // (px, py)
            const float2 rs = __ldg(&resolution[bt]);
            const float2 og = __ldg(&origin[bt]);

            const int col = (int)(pt.x / rs.x + og.x);   // trunc == astype(int)
            const int row = (int)(pt.y / rs.y + og.y);

            if (row >= 0 && row < H && col >= 0 && col < W) {  // JAX drops OOB
                const unsigned off =
                    ((bt * (unsigned)H + (unsigned)row) * (unsigned)W
                         + (unsigned)col) * (unsigned)P + l;
                if (off >= s && off < e) {
                    out[off] = 1.0f;
                }
            }
        }
        // No barrier needed at loop bottom: next iteration writes a disjoint
        // slice, and phase-2 writers re-sync against it via the top barrier.
        __syncthreads();
    }
}

// ---------------------------------------------------------------------------
extern "C" void kernel_launch(void* const* d_in, const int* in_sizes, int n_in,
                              void* d_out, int out_size) {
    const float2* x          = (const float2*)d_in[0];
    const float2* resolution = (const float2*)d_in[1];
    const float2* origin     = (const float2*)d_in[2];
    float* out = (float*)d_out;

    const unsigned n = (unsigned)out_size;           // 200,000,000 (div by 4)
    const unsigned n_vec4 = n / 4u;                  // 50,000,000
    const unsigned n_slices = (n + SLICE - 1u) / SLICE;   // 24415

    const unsigned blocks = (n_slices < (unsigned)PERSIST_BLOCKS)
                                ? n_slices : (unsigned)PERSIST_BLOCKS;

    fused_raster_kernel<<<blocks, ZTHREADS>>>(x, resolution, origin, out,
                                              n_vec4, n_slices);
}

// round 8
// speedup vs baseline: 1.1110x; 1.1110x over previous
#include <cuda_runtime.h>
#include <cstdint>

// Output: [B=16, T=50, H=100, W=100, P=25] fp32 = 200M elems = 800MB.
// Best configuration (R5 shape + R6 32-bit math):
// Single kernel, 48829 free-running CTAs. Each block zeroes a contiguous
// 4096-float slice (4x STG.128 evict-first), one __syncthreads (CTA-scope
// ordering only — no global fence), then warps 0-1 recompute the <=50
// candidate points of the <=2 bt-regions overlapping the slice and write
// 1.0f for those landing inside it. Every output offset belongs to exactly
// one slice -> exactly-once, race-free, deterministic.

static constexpr int B = 16;
static constexpr int T = 50;
static constexpr int H = 100;
static constexpr int W = 100;
static constexpr int P = 25;
static constexpr unsigned BT_STRIDE = (unsigned)H * W * P;   // 250000

static constexpr int VPT = 4;                        // float4s per thread (64B)
static constexpr int ZTHREADS = 256;
static constexpr unsigned SLICE = ZTHREADS * VPT * 4;        // 4096 floats

__global__ void __launch_bounds__(ZTHREADS)
fused_raster_kernel(const float2* __restrict__ x,          // [B*T*P] (px,py)
                    const float2* __restrict__ resolution, // [B*T]
                    const float2* __restrict__ origin,     // [B*T]
                    float* __restrict__ out,
                    unsigned n_vec4) {
    // ---- Phase 1: zero this block's slice (4x STG.128, evict-first) ----
    const float4 z = make_float4(0.f, 0.f, 0.f, 0.f);
    const unsigned base = blockIdx.x * (ZTHREADS * VPT) + threadIdx.x;
#pragma unroll
    for (int k = 0; k < VPT; k++) {
        unsigned i = base + k * ZTHREADS;
        if (i < n_vec4) {
            __stcs(reinterpret_cast<float4*>(out) + i, z);
        }
    }

    // CTA-scope ordering only: this block's zeros precede its ones (~7cyc BAR).
    __syncthreads();

    // ---- Phase 2: ones for offsets inside [s, e), all 32-bit math ----
    const unsigned n = n_vec4 * 4u;                  // 200,000,000 < 2^31
    const unsigned s = blockIdx.x * SLICE;
    const unsigned e = (s + SLICE < n) ? (s + SLICE) : n;

    const unsigned bt0 = s / BT_STRIDE;              // const-div -> mul/shift
    const unsigned bt1 = (e - 1u) / BT_STRIDE;       // slice spans <=2 regions
    const unsigned nbt = bt1 - bt0 + 1u;             // 1 or 2

    const unsigned w = threadIdx.x >> 5;
    const unsigned l = threadIdx.x & 31u;
    if (w < nbt && l < (unsigned)P) {
        const unsigned bt = bt0 + w;
        const float2 pt = __ldg(&x[bt * P + l]);     // (px, py)
        const float2 rs = __ldg(&resolution[bt]);
        const float2 og = __ldg(&origin[bt]);

        const int col = (int)(pt.x / rs.x + og.x);   // trunc == astype(int)
        const int row = (int)(pt.y / rs.y + og.y);

        if (row >= 0 && row < H && col >= 0 && col < W) {   // JAX drops OOB
            const unsigned off =
                ((bt * (unsigned)H + (unsigned)row) * (unsigned)W
                     + (unsigned)col) * (unsigned)P + l;
            if (off >= s && off < e) {
                out[off] = 1.0f;
            }
        }
    }
}

// ---------------------------------------------------------------------------
extern "C" void kernel_launch(void* const* d_in, const int* in_sizes, int n_in,
                              void* d_out, int out_size) {
    const float2* x          = (const float2*)d_in[0];
    const float2* resolution = (const float2*)d_in[1];
    const float2* origin     = (const float2*)d_in[2];
    float* out = (float*)d_out;

    const unsigned n = (unsigned)out_size;           // 200,000,000 (div by 4)
    const unsigned n_vec4 = n / 4u;                  // 50,000,000

    const unsigned slots = (n_vec4 + VPT - 1) / VPT;
    const unsigned blocks = (slots + ZTHREADS - 1) / ZTHREADS;   // 48829

    fused_raster_kernel<<<blocks, ZTHREADS>>>(x, resolution, origin, out, n_vec4);
}

// round 9
// speedup vs baseline: 1.1113x; 1.0003x over previous
#include <cuda_runtime.h>
#include <cstdint>

// Output: [B=16, T=50, H=100, W=100, P=25] fp32 = 200M elems = 800MB.
// Final form. Single kernel, 48829 free-running CTAs, one barrier each.
// Each block zeroes a contiguous 4096-float slice (4x STG.128 evict-first).
// Phase-2 (the <=50 candidate 1.0f points of the <=2 bt-regions overlapping
// the slice) is computed ENTIRELY BEFORE the barrier — input loads overlap
// the zero-store stream — leaving only the single out[off]=1.0f after
// __syncthreads (CTA-scope zero->one ordering; no global fence).
// Every output offset belongs to exactly one slice: exactly-once, race-free.

static constexpr int B = 16;
static constexpr int T = 50;
static constexpr int H = 100;
static constexpr int W = 100;
static constexpr int P = 25;
static constexpr unsigned BT_STRIDE = (unsigned)H * W * P;   // 250000

static constexpr int VPT = 4;                        // float4s per thread (64B)
static constexpr int ZTHREADS = 256;
static constexpr unsigned SLICE = ZTHREADS * VPT * 4;        // 4096 floats

__global__ void __launch_bounds__(ZTHREADS)
fused_raster_kernel(const float2* __restrict__ x,          // [B*T*P] (px,py)
                    const float2* __restrict__ resolution, // [B*T]
                    const float2* __restrict__ origin,     // [B*T]
                    float* __restrict__ out,
                    unsigned n_vec4) {
    // ---- Phase 2a (pre-barrier): compute this slice's candidate one-write.
    //      Touches only inputs, never `out` -> no hazard with the zeros.
    //      Loads issue early and their latency hides under the store stream.
    const unsigned n = n_vec4 * 4u;                  // 200,000,000 < 2^31
    const unsigned s = blockIdx.x * SLICE;
    const unsigned e = (s + SLICE < n) ? (s + SLICE) : n;

    const unsigned bt0 = s / BT_STRIDE;              // const-div -> mul/shift
    const unsigned bt1 = (e - 1u) / BT_STRIDE;       // slice spans <=2 regions
    const unsigned nbt = bt1 - bt0 + 1u;             // 1 or 2

    const unsigned w = threadIdx.x >> 5;
    const unsigned l = threadIdx.x & 31u;

    bool     do_write = false;
    unsigned off      = 0;
    if (w < nbt && l < (unsigned)P) {
        const unsigned bt = bt0 + w;
        const float2 pt = __ldg(&x[bt * P + l]);     // (px, py)
        const float2 rs = __ldg(&resolution[bt]);
        const float2 og = __ldg(&origin[bt]);

        const int col = (int)(pt.x / rs.x + og.x);   // trunc == astype(int)
        const int row = (int)(pt.y / rs.y + og.y);

        if (row >= 0 && row < H && col >= 0 && col < W) {   // JAX drops OOB
            off = ((bt * (unsigned)H + (unsigned)row) * (unsigned)W
                       + (unsigned)col) * (unsigned)P + l;
            do_write = (off >= s && off < e);
        }
    }

    // ---- Phase 1: zero this block's slice (4x STG.128, evict-first) ----
    const float4 z = make_float4(0.f, 0.f, 0.f, 0.f);
    const unsigned base = blockIdx.x * (ZTHREADS * VPT) + threadIdx.x;
#pragma unroll
    for (int k = 0; k < VPT; k++) {
        unsigned i = base + k * ZTHREADS;
        if (i < n_vec4) {
            __stcs(reinterpret_cast<float4*>(out) + i, z);
        }
    }

    // CTA-scope ordering: this block's zeros precede its ones.
    __syncthreads();

    // ---- Phase 2b (post-barrier): single store, ~5cyc tail ----
    if (do_write) {
        out[off] = 1.0f;
    }
}

// ---------------------------------------------------------------------------
extern "C" void kernel_launch(void* const* d_in, const int* in_sizes, int n_in,
                              void* d_out, int out_size) {
    const float2* x          = (const float2*)d_in[0];
    const float2* resolution = (const float2*)d_in[1];
    const float2* origin     = (const float2*)d_in[2];
    float* out = (float*)d_out;

    const unsigned n = (unsigned)out_size;           // 200,000,000 (div by 4)
    const unsigned n_vec4 = n / 4u;                  // 50,000,000

    const unsigned slots = (n_vec4 + VPT - 1) / VPT;
    const unsigned blocks = (slots + ZTHREADS - 1) / ZTHREADS;   // 48829

    fused_raster_kernel<<<blocks, ZTHREADS>>>(x, resolution, origin, out, n_vec4);
}